// round 1
// baseline (speedup 1.0000x reference)
#include <cuda_runtime.h>
#include <math.h>

#define MAXN 10000
#define MAXE 320000

// ---------------- scratch (device globals; no runtime alloc) ----------------
__device__ float g_s  [MAXN*32];    // node scalars (N,32)
__device__ float g_v  [MAXN*96];    // node vectors (N,3,32)  [n*96 + i*32 + u]
__device__ float g_scs[MAXN*32];
__device__ float g_scv[MAXN*96];
__device__ float g_xs [MAXN*32];
__device__ float g_xv [MAXN*96];
__device__ float g_aggs[MAXN*64];   // (N,64)
__device__ float g_aggv[MAXN*192];  // (N,3,64) [n*192 + i*64 + c]
__device__ float g_emb[MAXE*10];
__device__ float g_Y  [MAXE*3];

// ---------------- constants ----------------
#define SQRT3F   1.7320508075688772f
#define ISQRT3F  0.5773502691896258f
#define INV_NB   0.17677669529663687f   // 1/sqrt(32)
#define NORM128  0.08838834764831845f   // 1/sqrt(128)
#define NORM256  0.0625f                // 1/sqrt(256)
#define INVS10   0.3162277660168379f    // 1/sqrt(10)
#define C_S      0.3826834323650898f    // sin(pi/8)
#define C_X      0.9238795325112867f    // cos(pi/8)
#define PI_F     3.14159265358979f

// ---------------- precompute: edge geometry + radial basis ----------------
__global__ void k_pre_edges(const float* __restrict__ evec, int E) {
    int e = blockIdx.x * blockDim.x + threadIdx.x;
    if (e >= E) return;
    float vx = evec[e*3+0], vy = evec[e*3+1], vz = evec[e*3+2];
    float len = sqrtf(vx*vx + vy*vy + vz*vz);
    float inv = 1.0f / (len + 1e-9f);
    g_Y[e*3+0] = SQRT3F * vx * inv;
    g_Y[e*3+1] = SQRT3F * vy * inv;
    g_Y[e*3+2] = SQRT3F * vz * inv;
    // smooth cutoff: u = 2*(len/4 - 1)
    float u = 0.5f*len - 2.0f;
    float cut;
    if (u > 0.0f)       cut = 0.0f;
    else if (u < -1.0f) cut = 1.0f;
    else                cut = (1.0f - __cosf(PI_F * u)) * 0.5f;
#pragma unroll
    for (int b = 0; b < 10; b++) {
        float c = (4.0f/9.0f) * (float)b;        // linspace(0,4,10)
        float d = (len - c) * 2.5f;              // / (4/10)
        g_emb[e*10+b] = __expf(-d*d) * cut;
    }
}

// ---------------- precompute: unpack x into s,v (SoA) ----------------
__global__ void k_pre_nodes(const float* __restrict__ x, int N) {
    int i = blockIdx.x * blockDim.x + threadIdx.x;
    if (i >= N*32) return;
    int n = i >> 5, u = i & 31;
    g_s[i] = x[n*128 + u];
    g_v[n*96 +      u] = x[n*128 + 32 + u*3 + 0];
    g_v[n*96 + 32 + u] = x[n*128 + 32 + u*3 + 1];
    g_v[n*96 + 64 + u] = x[n*128 + 32 + u*3 + 2];
}

__global__ void k_zero_agg(int N) {
    int i = blockIdx.x * blockDim.x + threadIdx.x;
    int n64 = N*64;
    if (i < n64) g_aggs[i] = 0.0f;
    else if (i < n64 + N*192) g_aggv[i - n64] = 0.0f;
}

// ---------------- fctp #1: (s,v) x attr -> sc_s,sc_v and xs,xv ----------------
__global__ void k_fctp1(const float* __restrict__ attr,
                        const float* __restrict__ W0, const float* __restrict__ W1,
                        const float* __restrict__ L0, const float* __restrict__ L1,
                        int N) {
    extern __shared__ float sm[];
    float* s0 = sm;          float* s1 = sm + 4096;
    float* s2 = sm + 8192;   float* s3 = sm + 12288;
    for (int i = threadIdx.x; i < 4096; i += blockDim.x) {
        s0[i] = W0[i]; s1[i] = W1[i]; s2[i] = L0[i]; s3[i] = L1[i];
    }
    __syncthreads();
    int lane = threadIdx.x & 31;
    int wid  = blockIdx.x * (blockDim.x >> 5) + (threadIdx.x >> 5);
    int wstr = gridDim.x * (blockDim.x >> 5);
    for (int n = wid; n < N; n += wstr) {
        float sl = g_s[n*32 + lane];
        float v0 = g_v[n*96 + lane];
        float v1 = g_v[n*96 + 32 + lane];
        float v2 = g_v[n*96 + 64 + lane];
        float at0 = attr[n*4+0], at1 = attr[n*4+1], at2 = attr[n*4+2], at3 = attr[n*4+3];
        float at[4] = {at0, at1, at2, at3};
        float scs=0.f, xs=0.f, scv0=0.f, scv1=0.f, scv2=0.f, xv0=0.f, xv1=0.f, xv2=0.f;
        for (int u = 0; u < 32; u++) {
            float su  = __shfl_sync(0xffffffffu, sl, u);
            float vu0 = __shfl_sync(0xffffffffu, v0, u);
            float vu1 = __shfl_sync(0xffffffffu, v1, u);
            float vu2 = __shfl_sync(0xffffffffu, v2, u);
            int base = u*128 + lane;
#pragma unroll
            for (int a = 0; a < 4; a++) {
                float ca = at[a];
                int wi = base + a*32;
                float cs = su * ca;
                scs += cs * s0[wi];
                xs  += cs * s2[wi];
                float w1 = s1[wi], w2 = s3[wi];
                float c0 = vu0*ca, c1 = vu1*ca, c2 = vu2*ca;
                scv0 += c0*w1; scv1 += c1*w1; scv2 += c2*w1;
                xv0  += c0*w2; xv1  += c1*w2; xv2  += c2*w2;
            }
        }
        g_scs[n*32+lane] = scs*NORM128;
        g_xs [n*32+lane] = xs *NORM128;
        g_scv[n*96+lane]      = scv0*NORM128;
        g_scv[n*96+32+lane]   = scv1*NORM128;
        g_scv[n*96+64+lane]   = scv2*NORM128;
        g_xv [n*96+lane]      = xv0*NORM128;
        g_xv [n*96+32+lane]   = xv1*NORM128;
        g_xv [n*96+64+lane]   = xv2*NORM128;
    }
}

// ---------------- fused edge kernel: radial MLP + messages + atomic scatter ----
__global__ void __launch_bounds__(128)
k_edge(const int* __restrict__ esrc, const int* __restrict__ edst,
       const float* __restrict__ Wfc1, const float* __restrict__ Wfc2, int E) {
    __shared__ float shW1[640];
    __shared__ float shEmb[640];
    __shared__ __align__(16) float shH[64*64];
    __shared__ float shY[192];
    __shared__ int shSrc[64], shDst[64];
    int tid = threadIdx.x;
    int e0 = blockIdx.x * 64;
    int nE = E - e0; if (nE > 64) nE = 64;

    for (int i = tid; i < 640; i += 128) shW1[i] = Wfc1[i];
    // each thread owns one Wfc2 column (col = tid = k*32+u)
    float Wreg[64];
#pragma unroll
    for (int j = 0; j < 64; j++) Wreg[j] = Wfc2[j*128 + tid];

    for (int i = tid; i < nE*10; i += 128) shEmb[i] = g_emb[e0*10 + i];
    for (int i = tid; i < nE*3;  i += 128) shY[i]   = g_Y[e0*3 + i];
    if (tid < nE) { shSrc[tid] = esrc[e0+tid]; shDst[tid] = edst[e0+tid]; }
    __syncthreads();

    // phase 1: h = silu(emb @ Wfc1 / sqrt(10))
    for (int idx = tid; idx < nE*64; idx += 128) {
        int e = idx >> 6, j = idx & 63;
        float acc = 0.f;
#pragma unroll
        for (int b = 0; b < 10; b++) acc += shEmb[e*10+b] * shW1[b*64+j];
        acc *= INVS10;
        shH[idx] = acc / (1.0f + __expf(-acc));
    }
    __syncthreads();

    // phase 2: w[:,col] = (h @ Wfc2[:,col]) / 8 ; then message + atomic scatter
    int k = tid >> 5, u = tid & 31;
    for (int eb = 0; eb < nE; eb += 4) {
        float a0=0.f, a1=0.f, a2=0.f, a3=0.f;
        const float* h0 = &shH[(eb+0)*64];
        const float* h1 = &shH[(eb+1)*64];
        const float* h2 = &shH[(eb+2)*64];
        const float* h3 = &shH[(eb+3)*64];
#pragma unroll
        for (int j = 0; j < 64; j += 4) {
            float4 hA = *(const float4*)(h0 + j);
            float4 hB = *(const float4*)(h1 + j);
            float4 hC = *(const float4*)(h2 + j);
            float4 hD = *(const float4*)(h3 + j);
            a0 += hA.x*Wreg[j] + hA.y*Wreg[j+1] + hA.z*Wreg[j+2] + hA.w*Wreg[j+3];
            a1 += hB.x*Wreg[j] + hB.y*Wreg[j+1] + hB.z*Wreg[j+2] + hB.w*Wreg[j+3];
            a2 += hC.x*Wreg[j] + hC.y*Wreg[j+1] + hC.z*Wreg[j+2] + hC.w*Wreg[j+3];
            a3 += hD.x*Wreg[j] + hD.y*Wreg[j+1] + hD.z*Wreg[j+2] + hD.w*Wreg[j+3];
        }
        float wv[4] = {a0*0.125f, a1*0.125f, a2*0.125f, a3*0.125f};
#pragma unroll
        for (int t = 0; t < 4; t++) {
            int e = eb + t;
            if (e >= nE) break;
            float w = wv[t];
            int src = shSrc[e], dst = shDst[e];
            float Y0 = shY[e*3+0], Y1v = shY[e*3+1], Y2 = shY[e*3+2];
            if (k == 0) {
                float sE = g_xs[src*32 + u];
                atomicAdd(&g_aggs[dst*64 + u], w*sE*INV_NB);
            } else if (k == 1) {
                float b0 = g_xv[src*96 + u];
                float b1 = g_xv[src*96 + 32 + u];
                float b2 = g_xv[src*96 + 64 + u];
                float dot = Y0*b0 + Y1v*b1 + Y2*b2;
                atomicAdd(&g_aggs[dst*64 + 32 + u], w*dot*ISQRT3F*INV_NB);
            } else if (k == 2) {
                float sE = g_xs[src*32 + u];
                float m = w*sE*INV_NB;
                atomicAdd(&g_aggv[dst*192 +       u], m*Y0);
                atomicAdd(&g_aggv[dst*192 +  64 + u], m*Y1v);
                atomicAdd(&g_aggv[dst*192 + 128 + u], m*Y2);
            } else {
                float b0 = g_xv[src*96 + u];
                float b1 = g_xv[src*96 + 32 + u];
                float b2 = g_xv[src*96 + 64 + u];
                float m = w*INV_NB;
                atomicAdd(&g_aggv[dst*192 +  32 + u], m*b0);
                atomicAdd(&g_aggv[dst*192 +  96 + u], m*b1);
                atomicAdd(&g_aggv[dst*192 + 160 + u], m*b2);
            }
        }
    }
}

// ---------------- fctp #2 on aggregated messages + gated state update ----------
__global__ void k_fctp2(const float* __restrict__ attr,
                        const float* __restrict__ W20, const float* __restrict__ W21,
                        int N) {
    extern __shared__ float sm[];
    float* s0 = sm; float* s1 = sm + 8192;
    for (int i = threadIdx.x; i < 8192; i += blockDim.x) { s0[i] = W20[i]; s1[i] = W21[i]; }
    __syncthreads();
    int lane = threadIdx.x & 31;
    int wid  = blockIdx.x * (blockDim.x >> 5) + (threadIdx.x >> 5);
    int wstr = gridDim.x * (blockDim.x >> 5);
    for (int n = wid; n < N; n += wstr) {
        float sa = g_aggs[n*64 + lane],       sb = g_aggs[n*64 + 32 + lane];
        float va0 = g_aggv[n*192 + lane],       vb0 = g_aggv[n*192 + 32 + lane];
        float va1 = g_aggv[n*192 + 64 + lane],  vb1 = g_aggv[n*192 + 96 + lane];
        float va2 = g_aggv[n*192 + 128 + lane], vb2 = g_aggv[n*192 + 160 + lane];
        float at[4] = {attr[n*4+0], attr[n*4+1], attr[n*4+2], attr[n*4+3]};
        float os=0.f, ov0=0.f, ov1=0.f, ov2=0.f;
        for (int u = 0; u < 32; u++) {
            float su  = __shfl_sync(0xffffffffu, sa, u);
            float w0  = __shfl_sync(0xffffffffu, va0, u);
            float w1  = __shfl_sync(0xffffffffu, va1, u);
            float w2  = __shfl_sync(0xffffffffu, va2, u);
            int base = u*128 + lane;
#pragma unroll
            for (int a = 0; a < 4; a++) {
                float ca = at[a];
                int wi = base + a*32;
                os  += su*ca * s0[wi];
                float W = s1[wi];
                ov0 += w0*ca*W; ov1 += w1*ca*W; ov2 += w2*ca*W;
            }
        }
        for (int u = 0; u < 32; u++) {
            float su  = __shfl_sync(0xffffffffu, sb, u);
            float w0  = __shfl_sync(0xffffffffu, vb0, u);
            float w1  = __shfl_sync(0xffffffffu, vb1, u);
            float w2  = __shfl_sync(0xffffffffu, vb2, u);
            int base = (u+32)*128 + lane;
#pragma unroll
            for (int a = 0; a < 4; a++) {
                float ca = at[a];
                int wi = base + a*32;
                os  += su*ca * s0[wi];
                float W = s1[wi];
                ov0 += w0*ca*W; ov1 += w1*ca*W; ov2 += w2*ca*W;
            }
        }
        os *= NORM256; ov0 *= NORM256; ov1 *= NORM256; ov2 *= NORM256;
        float sn  = C_S * g_scs[n*32+lane] + C_X * os;
        float sig = 1.0f / (1.0f + __expf(-sn));
        g_s[n*32+lane] += sn * sig;
        float vn0 = C_S * g_scv[n*96+lane]      + C_X * ov0;
        float vn1 = C_S * g_scv[n*96+32+lane]   + C_X * ov1;
        float vn2 = C_S * g_scv[n*96+64+lane]   + C_X * ov2;
        g_v[n*96+lane]      += vn0 * sig;
        g_v[n*96+32+lane]   += vn1 * sig;
        g_v[n*96+64+lane]   += vn2 * sig;
    }
}

// ---------------- readout + pooling ----------------
__global__ void k_zero_out(float* out) { out[threadIdx.x] = 0.0f; }

__global__ void k_read(const float* __restrict__ attr, const int* __restrict__ batch,
                       const float* __restrict__ Wread, float* __restrict__ out,
                       int N, float poolscale) {
    __shared__ float shW[2048];   // (32,4,16)
    __shared__ float pool[128];
    for (int i = threadIdx.x; i < 2048; i += blockDim.x) shW[i] = Wread[i];
    if (threadIdx.x < 128) pool[threadIdx.x] = 0.0f;
    __syncthreads();
    int lane = threadIdx.x & 31;
    int wid  = blockIdx.x * (blockDim.x >> 5) + (threadIdx.x >> 5);
    int wstr = gridDim.x * (blockDim.x >> 5);
    int w = lane & 15;
    for (int n = wid; n < N; n += wstr) {
        float sl = g_s[n*32 + lane];
        float at[4] = {attr[n*4+0], attr[n*4+1], attr[n*4+2], attr[n*4+3]};
        float acc = 0.f;
        for (int u = 0; u < 32; u++) {
            float su = __shfl_sync(0xffffffffu, sl, u);
            int base = u*64 + w;
#pragma unroll
            for (int a = 0; a < 4; a++) acc += su*at[a]*shW[base + a*16];
        }
        if (lane < 16) {
            int g = batch[n];
            atomicAdd(&pool[g*16 + w], acc * NORM128 * poolscale);
        }
    }
    __syncthreads();
    if (threadIdx.x < 128) atomicAdd(&out[threadIdx.x], pool[threadIdx.x]);
}

// ---------------- launcher ----------------
extern "C" void kernel_launch(void* const* d_in, const int* in_sizes, int n_in,
                              void* d_out, int out_size) {
    const float* x    = (const float*)d_in[0];
    const float* attr = (const float*)d_in[1];
    const float* evec = (const float*)d_in[2];
    const int*   batch= (const int*)  d_in[3];
    const int*   esrc = (const int*)  d_in[4];
    const int*   edst = (const int*)  d_in[5];
    const float* Wsc0 = (const float*)d_in[6];
    const float* Wsc1 = (const float*)d_in[7];
    const float* Wl10 = (const float*)d_in[8];
    const float* Wl11 = (const float*)d_in[9];
    const float* Wfc1 = (const float*)d_in[10];
    const float* Wfc2 = (const float*)d_in[11];
    const float* Wl20 = (const float*)d_in[12];
    const float* Wl21 = (const float*)d_in[13];
    const float* Wread= (const float*)d_in[14];
    int N = in_sizes[0] / 128;
    int E = in_sizes[4];

    cudaFuncSetAttribute(k_fctp1, cudaFuncAttributeMaxDynamicSharedMemorySize, 65536);
    cudaFuncSetAttribute(k_fctp2, cudaFuncAttributeMaxDynamicSharedMemorySize, 65536);

    k_pre_edges<<<(E + 255) / 256, 256>>>(evec, E);
    k_pre_nodes<<<(N*32 + 255) / 256, 256>>>(x, N);

    for (int l = 0; l < 2; l++) {
        k_zero_agg<<<(N*256 + 255) / 256, 256>>>(N);
        k_fctp1<<<592, 128, 65536>>>(attr, Wsc0 + l*4096, Wsc1 + l*4096,
                                     Wl10 + l*4096, Wl11 + l*4096, N);
        k_edge<<<(E + 63) / 64, 128>>>(esrc, edst, Wfc1 + l*640, Wfc2 + l*8192, E);
        k_fctp2<<<592, 128, 65536>>>(attr, Wl20 + l*8192, Wl21 + l*8192, N);
    }

    k_zero_out<<<1, 128>>>((float*)d_out);
    float poolscale = 1.0f / sqrtf((float)N / 8.0f);
    k_read<<<592, 128>>>(attr, batch, Wread, (float*)d_out, N, poolscale);
}

// round 2
// speedup vs baseline: 1.1079x; 1.1079x over previous
#include <cuda_runtime.h>
#include <math.h>

#define MAXN 10000
#define MAXE 320000

// ---------------- scratch (device globals; no runtime alloc) ----------------
__device__ float g_s  [MAXN*32];
__device__ float g_v  [MAXN*96];    // (N,3,32)  [n*96 + i*32 + u]
__device__ float g_scs[MAXN*32];
__device__ float g_scv[MAXN*96];
__device__ float g_xs [MAXN*32];
__device__ float g_xv [MAXN*96];
__device__ float g_aggs[MAXN*64];   // (N,64)
__device__ float g_aggv[MAXN*192];  // (N,3,64)
// CSR (by dst) + permuted edge data
__device__ int   g_deg   [MAXN];
__device__ int   g_cursor[MAXN];
__device__ int   g_rowstart[MAXN+1];
__device__ int   g_slot  [MAXE];
__device__ int   g_srcP  [MAXE];
__device__ float g_embP  [MAXE*10];
__device__ float g_YP    [MAXE*3];

// ---------------- constants ----------------
#define SQRT3F   1.7320508075688772f
#define ISQRT3F  0.5773502691896258f
#define INV_NB   0.17677669529663687f   // 1/sqrt(32)
#define NORM128  0.08838834764831845f   // 1/sqrt(128)
#define NORM256  0.0625f                // 1/sqrt(256)
#define INVS10   0.3162277660168379f    // 1/sqrt(10)
#define C_S      0.3826834323650898f    // sin(pi/8)
#define C_X      0.9238795325112867f    // cos(pi/8)
#define PI_F     3.14159265358979f

// ---------------- packed f32x2 helpers ----------------
__device__ __forceinline__ unsigned long long pack2(float lo, float hi) {
    unsigned long long r;
    asm("mov.b64 %0, {%1, %2};" : "=l"(r) : "f"(lo), "f"(hi));
    return r;
}
__device__ __forceinline__ void ffma2(unsigned long long& acc,
                                      unsigned long long a, unsigned long long b) {
    asm("fma.rn.f32x2 %0, %1, %2, %0;" : "+l"(acc) : "l"(a), "l"(b));
}
__device__ __forceinline__ float2 unpack2(unsigned long long v) {
    float2 f;
    asm("mov.b64 {%0, %1}, %2;" : "=f"(f.x), "=f"(f.y) : "l"(v));
    return f;
}

// ---------------- CSR build ----------------
__global__ void k_zero_deg(int N) {
    int i = blockIdx.x * blockDim.x + threadIdx.x;
    if (i < N) g_deg[i] = 0;
}
__global__ void k_hist(const int* __restrict__ edst, int E) {
    int e = blockIdx.x * blockDim.x + threadIdx.x;
    if (e < E) atomicAdd(&g_deg[edst[e]], 1);
}
#define SCAN_T 1024
__global__ void k_scan(int N) {
    __shared__ int sums[SCAN_T];
    int t = threadIdx.x;
    int IT = (N + SCAN_T - 1) / SCAN_T;
    int lo = t * IT, hi = lo + IT; if (hi > N) hi = N; if (lo > N) lo = N;
    int s = 0;
    for (int i = lo; i < hi; i++) s += g_deg[i];
    sums[t] = s;
    __syncthreads();
    for (int off = 1; off < SCAN_T; off <<= 1) {
        int v = (t >= off) ? sums[t - off] : 0;
        __syncthreads();
        sums[t] += v;
        __syncthreads();
    }
    int run = (t == 0) ? 0 : sums[t - 1];
    for (int i = lo; i < hi; i++) {
        g_rowstart[i] = run;
        g_cursor[i]   = run;
        run += g_deg[i];
    }
    if (hi == N) g_rowstart[N] = run;
}
__global__ void k_fill(const int* __restrict__ esrc, const int* __restrict__ edst, int E) {
    int e = blockIdx.x * blockDim.x + threadIdx.x;
    if (e >= E) return;
    int pos = atomicAdd(&g_cursor[edst[e]], 1);
    g_slot[e] = pos;
    g_srcP[pos] = esrc[e];
}

// ---------------- precompute: edge geometry + radial basis (permuted write) ----
__global__ void k_pre_edges(const float* __restrict__ evec, int E) {
    int e = blockIdx.x * blockDim.x + threadIdx.x;
    if (e >= E) return;
    int p = g_slot[e];
    float vx = evec[e*3+0], vy = evec[e*3+1], vz = evec[e*3+2];
    float len = sqrtf(vx*vx + vy*vy + vz*vz);
    float inv = 1.0f / (len + 1e-9f);
    g_YP[p*3+0] = SQRT3F * vx * inv;
    g_YP[p*3+1] = SQRT3F * vy * inv;
    g_YP[p*3+2] = SQRT3F * vz * inv;
    float u = 0.5f*len - 2.0f;
    float cut;
    if (u > 0.0f)       cut = 0.0f;
    else if (u < -1.0f) cut = 1.0f;
    else                cut = (1.0f - __cosf(PI_F * u)) * 0.5f;
#pragma unroll
    for (int b = 0; b < 10; b++) {
        float c = (4.0f/9.0f) * (float)b;
        float d = (len - c) * 2.5f;
        g_embP[p*10+b] = __expf(-d*d) * cut;
    }
}

__global__ void k_pre_nodes(const float* __restrict__ x, int N) {
    int i = blockIdx.x * blockDim.x + threadIdx.x;
    if (i >= N*32) return;
    int n = i >> 5, u = i & 31;
    g_s[i] = x[n*128 + u];
    g_v[n*96 +      u] = x[n*128 + 32 + u*3 + 0];
    g_v[n*96 + 32 + u] = x[n*128 + 32 + u*3 + 1];
    g_v[n*96 + 64 + u] = x[n*128 + 32 + u*3 + 2];
}

// ---------------- fctp #1 ----------------
__global__ void k_fctp1(const float* __restrict__ attr,
                        const float* __restrict__ W0, const float* __restrict__ W1,
                        const float* __restrict__ L0, const float* __restrict__ L1,
                        int N) {
    extern __shared__ float sm[];
    float* s0 = sm;          float* s1 = sm + 4096;
    float* s2 = sm + 8192;   float* s3 = sm + 12288;
    for (int i = threadIdx.x; i < 4096; i += blockDim.x) {
        s0[i] = W0[i]; s1[i] = W1[i]; s2[i] = L0[i]; s3[i] = L1[i];
    }
    __syncthreads();
    int lane = threadIdx.x & 31;
    int wid  = blockIdx.x * (blockDim.x >> 5) + (threadIdx.x >> 5);
    int wstr = gridDim.x * (blockDim.x >> 5);
    for (int n = wid; n < N; n += wstr) {
        float sl = g_s[n*32 + lane];
        float v0 = g_v[n*96 + lane];
        float v1 = g_v[n*96 + 32 + lane];
        float v2 = g_v[n*96 + 64 + lane];
        float at[4] = {attr[n*4+0], attr[n*4+1], attr[n*4+2], attr[n*4+3]};
        float scs=0.f, xs=0.f, scv0=0.f, scv1=0.f, scv2=0.f, xv0=0.f, xv1=0.f, xv2=0.f;
        for (int u = 0; u < 32; u++) {
            float su  = __shfl_sync(0xffffffffu, sl, u);
            float vu0 = __shfl_sync(0xffffffffu, v0, u);
            float vu1 = __shfl_sync(0xffffffffu, v1, u);
            float vu2 = __shfl_sync(0xffffffffu, v2, u);
            int base = u*128 + lane;
#pragma unroll
            for (int a = 0; a < 4; a++) {
                float ca = at[a];
                int wi = base + a*32;
                float cs = su * ca;
                scs += cs * s0[wi];
                xs  += cs * s2[wi];
                float w1 = s1[wi], w2 = s3[wi];
                float c0 = vu0*ca, c1 = vu1*ca, c2 = vu2*ca;
                scv0 += c0*w1; scv1 += c1*w1; scv2 += c2*w1;
                xv0  += c0*w2; xv1  += c1*w2; xv2  += c2*w2;
            }
        }
        g_scs[n*32+lane] = scs*NORM128;
        g_xs [n*32+lane] = xs *NORM128;
        g_scv[n*96+lane]      = scv0*NORM128;
        g_scv[n*96+32+lane]   = scv1*NORM128;
        g_scv[n*96+64+lane]   = scv2*NORM128;
        g_xv [n*96+lane]      = xv0*NORM128;
        g_xv [n*96+32+lane]   = xv1*NORM128;
        g_xv [n*96+64+lane]   = xv2*NORM128;
    }
}

// ---------------- gather edge kernel: radial MLP + messages, NO atomics -------
#define TILE_E 32
__global__ void __launch_bounds__(128)
k_gather(const float* __restrict__ Wfc1, const float* __restrict__ Wfc2, int N) {
    __shared__ float shW1[640];
    __shared__ __align__(16) float shH[(TILE_E + 2) * 64];
    __shared__ float shEmb[TILE_E * 10];
    __shared__ float shY[TILE_E * 3];
    __shared__ int   shSrc[TILE_E];
    int tid = threadIdx.x;
    int k = tid >> 5, u = tid & 31;

    for (int i = tid; i < 640; i += 128) shW1[i] = Wfc1[i];
    // packed Wfc2 column pairs: Wp[j] = {Wfc2[2j][tid], Wfc2[2j+1][tid]}
    unsigned long long Wp[32];
#pragma unroll
    for (int j = 0; j < 32; j++)
        Wp[j] = pack2(Wfc2[(2*j)*128 + tid], Wfc2[(2*j+1)*128 + tid]);

    for (int n = blockIdx.x; n < N; n += gridDim.x) {
        int t0 = g_rowstart[n];
        int deg = g_rowstart[n+1] - t0;
        float acc0 = 0.f, acc1 = 0.f, acc2 = 0.f;

        for (int base = 0; base < deg; base += TILE_E) {
            int nT = deg - base; if (nT > TILE_E) nT = TILE_E;
            int eg0 = t0 + base;
            __syncthreads();
            for (int i = tid; i < nT*10; i += 128) shEmb[i] = g_embP[eg0*10 + i];
            for (int i = tid; i < nT*3;  i += 128) shY[i]   = g_YP[eg0*3 + i];
            if (tid < nT) shSrc[tid] = g_srcP[eg0 + tid];
            __syncthreads();

            // phase 1: h = silu(emb @ Wfc1 / sqrt(10)), layout [e*64 + j]
            for (int idx = tid; idx < nT*64; idx += 128) {
                int e = idx >> 6, j = idx & 63;
                float acc = 0.f;
#pragma unroll
                for (int b = 0; b < 10; b++) acc += shEmb[e*10+b] * shW1[b*64+j];
                acc *= INVS10;
                shH[idx] = acc / (1.0f + __expf(-acc));
            }
            if (nT & 1) { // zero-pad one edge row for the packed 2-edge loop
                for (int i = tid; i < 64; i += 128) shH[nT*64 + i] = 0.f;
            }
            __syncthreads();

            // phase 2: per thread, w = (h @ Wfc2[:,tid]) / 8, 2 edges at a time
            for (int eb = 0; eb < nT; eb += 2) {
                unsigned long long accA = 0ull, accB = 0ull;
                const ulonglong2* hA = (const ulonglong2*)&shH[eb*64];
                const ulonglong2* hB = (const ulonglong2*)&shH[(eb+1)*64];
#pragma unroll
                for (int q = 0; q < 16; q++) {
                    ulonglong2 a = hA[q];
                    ulonglong2 b = hB[q];
                    ffma2(accA, a.x, Wp[2*q]);
                    ffma2(accA, a.y, Wp[2*q+1]);
                    ffma2(accB, b.x, Wp[2*q]);
                    ffma2(accB, b.y, Wp[2*q+1]);
                }
                float2 fa = unpack2(accA);
                float2 fb = unpack2(accB);
                float wv[2] = {(fa.x + fa.y) * 0.125f, (fb.x + fb.y) * 0.125f};
#pragma unroll
                for (int t = 0; t < 2; t++) {
                    int e = eb + t;
                    if (e >= nT) break;
                    float w = wv[t];
                    int src = shSrc[e];
                    if (k == 0) {
                        acc0 += w * g_xs[src*32 + u];
                    } else if (k == 1) {
                        float b0 = g_xv[src*96 + u];
                        float b1 = g_xv[src*96 + 32 + u];
                        float b2 = g_xv[src*96 + 64 + u];
                        acc0 += w * (shY[e*3+0]*b0 + shY[e*3+1]*b1 + shY[e*3+2]*b2);
                    } else if (k == 2) {
                        float m = w * g_xs[src*32 + u];
                        acc0 += m * shY[e*3+0];
                        acc1 += m * shY[e*3+1];
                        acc2 += m * shY[e*3+2];
                    } else {
                        acc0 += w * g_xv[src*96 + u];
                        acc1 += w * g_xv[src*96 + 32 + u];
                        acc2 += w * g_xv[src*96 + 64 + u];
                    }
                }
            }
        }
        // write aggregated messages (no atomics)
        if (k == 0) {
            g_aggs[n*64 + u] = acc0 * INV_NB;
        } else if (k == 1) {
            g_aggs[n*64 + 32 + u] = acc0 * ISQRT3F * INV_NB;
        } else if (k == 2) {
            g_aggv[n*192 +       u] = acc0 * INV_NB;
            g_aggv[n*192 +  64 + u] = acc1 * INV_NB;
            g_aggv[n*192 + 128 + u] = acc2 * INV_NB;
        } else {
            g_aggv[n*192 +  32 + u] = acc0 * INV_NB;
            g_aggv[n*192 +  96 + u] = acc1 * INV_NB;
            g_aggv[n*192 + 160 + u] = acc2 * INV_NB;
        }
    }
}

// ---------------- fctp #2 + gated state update ----------------
__global__ void k_fctp2(const float* __restrict__ attr,
                        const float* __restrict__ W20, const float* __restrict__ W21,
                        int N) {
    extern __shared__ float sm[];
    float* s0 = sm; float* s1 = sm + 8192;
    for (int i = threadIdx.x; i < 8192; i += blockDim.x) { s0[i] = W20[i]; s1[i] = W21[i]; }
    __syncthreads();
    int lane = threadIdx.x & 31;
    int wid  = blockIdx.x * (blockDim.x >> 5) + (threadIdx.x >> 5);
    int wstr = gridDim.x * (blockDim.x >> 5);
    for (int n = wid; n < N; n += wstr) {
        float sa = g_aggs[n*64 + lane],       sb = g_aggs[n*64 + 32 + lane];
        float va0 = g_aggv[n*192 + lane],       vb0 = g_aggv[n*192 + 32 + lane];
        float va1 = g_aggv[n*192 + 64 + lane],  vb1 = g_aggv[n*192 + 96 + lane];
        float va2 = g_aggv[n*192 + 128 + lane], vb2 = g_aggv[n*192 + 160 + lane];
        float at[4] = {attr[n*4+0], attr[n*4+1], attr[n*4+2], attr[n*4+3]};
        float os=0.f, ov0=0.f, ov1=0.f, ov2=0.f;
        for (int u = 0; u < 32; u++) {
            float su  = __shfl_sync(0xffffffffu, sa, u);
            float w0  = __shfl_sync(0xffffffffu, va0, u);
            float w1  = __shfl_sync(0xffffffffu, va1, u);
            float w2  = __shfl_sync(0xffffffffu, va2, u);
            int base = u*128 + lane;
#pragma unroll
            for (int a = 0; a < 4; a++) {
                float ca = at[a];
                int wi = base + a*32;
                os  += su*ca * s0[wi];
                float W = s1[wi];
                ov0 += w0*ca*W; ov1 += w1*ca*W; ov2 += w2*ca*W;
            }
        }
        for (int u = 0; u < 32; u++) {
            float su  = __shfl_sync(0xffffffffu, sb, u);
            float w0  = __shfl_sync(0xffffffffu, vb0, u);
            float w1  = __shfl_sync(0xffffffffu, vb1, u);
            float w2  = __shfl_sync(0xffffffffu, vb2, u);
            int base = (u+32)*128 + lane;
#pragma unroll
            for (int a = 0; a < 4; a++) {
                float ca = at[a];
                int wi = base + a*32;
                os  += su*ca * s0[wi];
                float W = s1[wi];
                ov0 += w0*ca*W; ov1 += w1*ca*W; ov2 += w2*ca*W;
            }
        }
        os *= NORM256; ov0 *= NORM256; ov1 *= NORM256; ov2 *= NORM256;
        float sn  = C_S * g_scs[n*32+lane] + C_X * os;
        float sig = 1.0f / (1.0f + __expf(-sn));
        g_s[n*32+lane] += sn * sig;
        float vn0 = C_S * g_scv[n*96+lane]      + C_X * ov0;
        float vn1 = C_S * g_scv[n*96+32+lane]   + C_X * ov1;
        float vn2 = C_S * g_scv[n*96+64+lane]   + C_X * ov2;
        g_v[n*96+lane]      += vn0 * sig;
        g_v[n*96+32+lane]   += vn1 * sig;
        g_v[n*96+64+lane]   += vn2 * sig;
    }
}

// ---------------- readout + pooling ----------------
__global__ void k_zero_out(float* out) { out[threadIdx.x] = 0.0f; }

__global__ void k_read(const float* __restrict__ attr, const int* __restrict__ batch,
                       const float* __restrict__ Wread, float* __restrict__ out,
                       int N, float poolscale) {
    __shared__ float shW[2048];
    __shared__ float pool[128];
    for (int i = threadIdx.x; i < 2048; i += blockDim.x) shW[i] = Wread[i];
    if (threadIdx.x < 128) pool[threadIdx.x] = 0.0f;
    __syncthreads();
    int lane = threadIdx.x & 31;
    int wid  = blockIdx.x * (blockDim.x >> 5) + (threadIdx.x >> 5);
    int wstr = gridDim.x * (blockDim.x >> 5);
    int w = lane & 15;
    for (int n = wid; n < N; n += wstr) {
        float sl = g_s[n*32 + lane];
        float at[4] = {attr[n*4+0], attr[n*4+1], attr[n*4+2], attr[n*4+3]};
        float acc = 0.f;
        for (int u = 0; u < 32; u++) {
            float su = __shfl_sync(0xffffffffu, sl, u);
            int base = u*64 + w;
#pragma unroll
            for (int a = 0; a < 4; a++) acc += su*at[a]*shW[base + a*16];
        }
        if (lane < 16) {
            int g = batch[n];
            atomicAdd(&pool[g*16 + w], acc * NORM128 * poolscale);
        }
    }
    __syncthreads();
    if (threadIdx.x < 128) atomicAdd(&out[threadIdx.x], pool[threadIdx.x]);
}

// ---------------- launcher ----------------
extern "C" void kernel_launch(void* const* d_in, const int* in_sizes, int n_in,
                              void* d_out, int out_size) {
    const float* x    = (const float*)d_in[0];
    const float* attr = (const float*)d_in[1];
    const float* evec = (const float*)d_in[2];
    const int*   batch= (const int*)  d_in[3];
    const int*   esrc = (const int*)  d_in[4];
    const int*   edst = (const int*)  d_in[5];
    const float* Wsc0 = (const float*)d_in[6];
    const float* Wsc1 = (const float*)d_in[7];
    const float* Wl10 = (const float*)d_in[8];
    const float* Wl11 = (const float*)d_in[9];
    const float* Wfc1 = (const float*)d_in[10];
    const float* Wfc2 = (const float*)d_in[11];
    const float* Wl20 = (const float*)d_in[12];
    const float* Wl21 = (const float*)d_in[13];
    const float* Wread= (const float*)d_in[14];
    int N = in_sizes[0] / 128;
    int E = in_sizes[4];

    cudaFuncSetAttribute(k_fctp1, cudaFuncAttributeMaxDynamicSharedMemorySize, 65536);
    cudaFuncSetAttribute(k_fctp2, cudaFuncAttributeMaxDynamicSharedMemorySize, 65536);

    // CSR build (by dst) + permuted precompute
    k_zero_deg<<<(N + 255) / 256, 256>>>(N);
    k_hist<<<(E + 255) / 256, 256>>>(edst, E);
    k_scan<<<1, SCAN_T>>>(N);
    k_fill<<<(E + 255) / 256, 256>>>(esrc, edst, E);
    k_pre_edges<<<(E + 255) / 256, 256>>>(evec, E);
    k_pre_nodes<<<(N*32 + 255) / 256, 256>>>(x, N);

    for (int l = 0; l < 2; l++) {
        k_fctp1<<<444, 256, 65536>>>(attr, Wsc0 + l*4096, Wsc1 + l*4096,
                                     Wl10 + l*4096, Wl11 + l*4096, N);
        k_gather<<<1480, 128>>>(Wfc1 + l*640, Wfc2 + l*8192, N);
        k_fctp2<<<444, 256, 65536>>>(attr, Wl20 + l*8192, Wl21 + l*8192, N);
    }

    k_zero_out<<<1, 128>>>((float*)d_out);
    float poolscale = 1.0f / sqrtf((float)N / 8.0f);
    k_read<<<592, 128>>>(attr, batch, Wread, (float*)d_out, N, poolscale);
}

// round 3
// speedup vs baseline: 1.1882x; 1.0724x over previous
#include <cuda_runtime.h>
#include <math.h>

#define MAXN 10000
#define MAXE 320000

// ---------------- scratch (device globals; no runtime alloc) ----------------
__device__ float g_s  [MAXN*32];
__device__ float g_v  [MAXN*96];    // (N,3,32)  [n*96 + i*32 + u]
__device__ float g_scs[MAXN*32];
__device__ float g_scv[MAXN*96];
__device__ float g_xs [MAXN*32];
__device__ float g_xv [MAXN*96];
__device__ float g_aggs[MAXN*64];   // (N,64)
__device__ float g_aggv[MAXN*192];  // (N,3,64)
// CSR (by dst) + permuted edge data
__device__ int   g_deg   [MAXN];
__device__ int   g_cursor[MAXN];
__device__ int   g_rowstart[MAXN+1];
__device__ int   g_slot  [MAXE];
__device__ int   g_srcP  [MAXE];
__device__ float g_embP  [MAXE*10];
__device__ float g_YP    [MAXE*3];
// per-edge radial weights (E x 128), written by k_wgemm, read by k_gather2
__device__ float g_w     [MAXE*128];

// ---------------- constants ----------------
#define SQRT3F   1.7320508075688772f
#define ISQRT3F  0.5773502691896258f
#define INV_NB   0.17677669529663687f   // 1/sqrt(32)
#define NORM128  0.08838834764831845f   // 1/sqrt(128)
#define NORM256  0.0625f                // 1/sqrt(256)
#define INVS10   0.3162277660168379f    // 1/sqrt(10)
#define C_S      0.3826834323650898f    // sin(pi/8)
#define C_X      0.9238795325112867f    // cos(pi/8)
#define PI_F     3.14159265358979f

// ---------------- packed f32x2 helpers ----------------
__device__ __forceinline__ unsigned long long pack2(float lo, float hi) {
    unsigned long long r;
    asm("mov.b64 %0, {%1, %2};" : "=l"(r) : "f"(lo), "f"(hi));
    return r;
}
__device__ __forceinline__ void ffma2(unsigned long long& acc,
                                      unsigned long long a, unsigned long long b) {
    asm("fma.rn.f32x2 %0, %1, %2, %0;" : "+l"(acc) : "l"(a), "l"(b));
}
__device__ __forceinline__ void mul2(unsigned long long& v, unsigned long long s) {
    asm("mul.rn.f32x2 %0, %0, %1;" : "+l"(v) : "l"(s));
}

// ---------------- CSR build ----------------
__global__ void k_zero_deg(int N) {
    int i = blockIdx.x * blockDim.x + threadIdx.x;
    if (i < N) g_deg[i] = 0;
}
__global__ void k_hist(const int* __restrict__ edst, int E) {
    int e = blockIdx.x * blockDim.x + threadIdx.x;
    if (e < E) atomicAdd(&g_deg[edst[e]], 1);
}
#define SCAN_T 1024
__global__ void k_scan(int N) {
    __shared__ int sums[SCAN_T];
    int t = threadIdx.x;
    int IT = (N + SCAN_T - 1) / SCAN_T;
    int lo = t * IT, hi = lo + IT; if (hi > N) hi = N; if (lo > N) lo = N;
    int s = 0;
    for (int i = lo; i < hi; i++) s += g_deg[i];
    sums[t] = s;
    __syncthreads();
    for (int off = 1; off < SCAN_T; off <<= 1) {
        int v = (t >= off) ? sums[t - off] : 0;
        __syncthreads();
        sums[t] += v;
        __syncthreads();
    }
    int run = (t == 0) ? 0 : sums[t - 1];
    for (int i = lo; i < hi; i++) {
        g_rowstart[i] = run;
        g_cursor[i]   = run;
        run += g_deg[i];
    }
    if (hi == N) g_rowstart[N] = run;
}
__global__ void k_fill(const int* __restrict__ esrc, const int* __restrict__ edst, int E) {
    int e = blockIdx.x * blockDim.x + threadIdx.x;
    if (e >= E) return;
    int pos = atomicAdd(&g_cursor[edst[e]], 1);
    g_slot[e] = pos;
    g_srcP[pos] = esrc[e];
}

// ---------------- precompute: edge geometry + radial basis (permuted write) ----
__global__ void k_pre_edges(const float* __restrict__ evec, int E) {
    int e = blockIdx.x * blockDim.x + threadIdx.x;
    if (e >= E) return;
    int p = g_slot[e];
    float vx = evec[e*3+0], vy = evec[e*3+1], vz = evec[e*3+2];
    float len = sqrtf(vx*vx + vy*vy + vz*vz);
    float inv = 1.0f / (len + 1e-9f);
    g_YP[p*3+0] = SQRT3F * vx * inv;
    g_YP[p*3+1] = SQRT3F * vy * inv;
    g_YP[p*3+2] = SQRT3F * vz * inv;
    float u = 0.5f*len - 2.0f;
    float cut;
    if (u > 0.0f)       cut = 0.0f;
    else if (u < -1.0f) cut = 1.0f;
    else                cut = (1.0f - __cosf(PI_F * u)) * 0.5f;
#pragma unroll
    for (int b = 0; b < 10; b++) {
        float c = (4.0f/9.0f) * (float)b;
        float d = (len - c) * 2.5f;
        g_embP[p*10+b] = __expf(-d*d) * cut;
    }
}

__global__ void k_pre_nodes(const float* __restrict__ x, int N) {
    int i = blockIdx.x * blockDim.x + threadIdx.x;
    if (i >= N*32) return;
    int n = i >> 5, u = i & 31;
    g_s[i] = x[n*128 + u];
    g_v[n*96 +      u] = x[n*128 + 32 + u*3 + 0];
    g_v[n*96 + 32 + u] = x[n*128 + 32 + u*3 + 1];
    g_v[n*96 + 64 + u] = x[n*128 + 32 + u*3 + 2];
}

// ---------------- fctp #1 ----------------
__global__ void k_fctp1(const float* __restrict__ attr,
                        const float* __restrict__ W0, const float* __restrict__ W1,
                        const float* __restrict__ L0, const float* __restrict__ L1,
                        int N) {
    extern __shared__ float sm[];
    float* s0 = sm;          float* s1 = sm + 4096;
    float* s2 = sm + 8192;   float* s3 = sm + 12288;
    for (int i = threadIdx.x; i < 4096; i += blockDim.x) {
        s0[i] = W0[i]; s1[i] = W1[i]; s2[i] = L0[i]; s3[i] = L1[i];
    }
    __syncthreads();
    int lane = threadIdx.x & 31;
    int wid  = blockIdx.x * (blockDim.x >> 5) + (threadIdx.x >> 5);
    int wstr = gridDim.x * (blockDim.x >> 5);
    for (int n = wid; n < N; n += wstr) {
        float sl = g_s[n*32 + lane];
        float v0 = g_v[n*96 + lane];
        float v1 = g_v[n*96 + 32 + lane];
        float v2 = g_v[n*96 + 64 + lane];
        float at[4] = {attr[n*4+0], attr[n*4+1], attr[n*4+2], attr[n*4+3]};
        float scs=0.f, xs=0.f, scv0=0.f, scv1=0.f, scv2=0.f, xv0=0.f, xv1=0.f, xv2=0.f;
        for (int u = 0; u < 32; u++) {
            float su  = __shfl_sync(0xffffffffu, sl, u);
            float vu0 = __shfl_sync(0xffffffffu, v0, u);
            float vu1 = __shfl_sync(0xffffffffu, v1, u);
            float vu2 = __shfl_sync(0xffffffffu, v2, u);
            int base = u*128 + lane;
#pragma unroll
            for (int a = 0; a < 4; a++) {
                float ca = at[a];
                int wi = base + a*32;
                float cs = su * ca;
                scs += cs * s0[wi];
                xs  += cs * s2[wi];
                float w1 = s1[wi], w2 = s3[wi];
                float c0 = vu0*ca, c1 = vu1*ca, c2 = vu2*ca;
                scv0 += c0*w1; scv1 += c1*w1; scv2 += c2*w1;
                xv0  += c0*w2; xv1  += c1*w2; xv2  += c2*w2;
            }
        }
        g_scs[n*32+lane] = scs*NORM128;
        g_xs [n*32+lane] = xs *NORM128;
        g_scv[n*96+lane]      = scv0*NORM128;
        g_scv[n*96+32+lane]   = scv1*NORM128;
        g_scv[n*96+64+lane]   = scv2*NORM128;
        g_xv [n*96+lane]      = xv0*NORM128;
        g_xv [n*96+32+lane]   = xv1*NORM128;
        g_xv [n*96+64+lane]   = xv2*NORM128;
    }
}

// ---------------- w-GEMM: h = silu(emb@W1), w = h@W2/8 -> g_w ----------------
#define WG_TE 128
__global__ void __launch_bounds__(256)
k_wgemm(const float* __restrict__ Wfc1, const float* __restrict__ Wfc2, int E) {
    __shared__ float shW1[640];
    __shared__ __align__(16) float shW2[64*128];     // 32 KB
    __shared__ float shEmb[WG_TE*10];                // 5 KB
    __shared__ float shH[WG_TE*65];                  // 33.3 KB (padded stride)
    int tid = threadIdx.x;
    int eg0 = blockIdx.x * WG_TE;
    int nE = E - eg0; if (nE > WG_TE) nE = WG_TE;

    for (int i = tid; i < 640; i += 256) shW1[i] = Wfc1[i];
    for (int i = tid; i < 8192; i += 256) shW2[i] = Wfc2[i];
    for (int i = tid; i < WG_TE*10; i += 256) shEmb[i] = (i < nE*10) ? g_embP[eg0*10 + i] : 0.f;
    __syncthreads();

    // phase 1: h[e][k]
    for (int idx = tid; idx < WG_TE*64; idx += 256) {
        int e = idx >> 6, k = idx & 63;
        float acc = 0.f;
#pragma unroll
        for (int b = 0; b < 10; b++) acc += shEmb[e*10+b] * shW1[b*64+k];
        acc *= INVS10;
        shH[e*65 + k] = acc / (1.0f + __expf(-acc));
    }
    __syncthreads();

    // phase 2: 8x8 register tile per thread, packed along columns
    int c0 = (tid & 15) * 8;           // column group
    int e0 = (tid >> 4) * 8;           // edge group
    unsigned long long acc[8][4];
#pragma unroll
    for (int e = 0; e < 8; e++)
#pragma unroll
        for (int c = 0; c < 4; c++) acc[e][c] = 0ull;

#pragma unroll 4
    for (int k = 0; k < 64; k++) {
        const unsigned long long* Wrow = (const unsigned long long*)&shW2[k*128 + c0];
        unsigned long long w0 = Wrow[0], w1 = Wrow[1], w2 = Wrow[2], w3 = Wrow[3];
#pragma unroll
        for (int e = 0; e < 8; e++) {
            float hv = shH[(e0+e)*65 + k];
            unsigned long long hp = pack2(hv, hv);
            ffma2(acc[e][0], hp, w0);
            ffma2(acc[e][1], hp, w1);
            ffma2(acc[e][2], hp, w2);
            ffma2(acc[e][3], hp, w3);
        }
    }

    // epilogue: scale by 1/8 and store (two STG.128 per edge row)
    unsigned long long sc = pack2(0.125f, 0.125f);
#pragma unroll
    for (int e = 0; e < 8; e++) {
        int ge = eg0 + e0 + e;
        if (ge >= E) break;
        mul2(acc[e][0], sc); mul2(acc[e][1], sc);
        mul2(acc[e][2], sc); mul2(acc[e][3], sc);
        ulonglong2* dst = (ulonglong2*)&g_w[ge*128 + c0];
        dst[0] = make_ulonglong2(acc[e][0], acc[e][1]);
        dst[1] = make_ulonglong2(acc[e][2], acc[e][3]);
    }
}

// ---------------- gather kernel: read w, gather features, accumulate ----------
__global__ void __launch_bounds__(128)
k_gather2(int N) {
    int n = blockIdx.x;
    if (n >= N) return;
    int tid = threadIdx.x;
    int k = tid >> 5, u = tid & 31;
    int t0 = g_rowstart[n];
    int t1 = g_rowstart[n+1];
    float a0 = 0.f, a1 = 0.f, a2 = 0.f;

    if (k == 0) {
        for (int e = t0; e < t1; e++) {
            float w = g_w[e*128 + tid];
            int src = g_srcP[e];
            a0 += w * g_xs[src*32 + u];
        }
        g_aggs[n*64 + u] = a0 * INV_NB;
    } else if (k == 1) {
        for (int e = t0; e < t1; e++) {
            float w = g_w[e*128 + tid];
            int src = g_srcP[e];
            float b0 = g_xv[src*96 + u];
            float b1 = g_xv[src*96 + 32 + u];
            float b2 = g_xv[src*96 + 64 + u];
            float Y0 = g_YP[e*3+0], Y1 = g_YP[e*3+1], Y2 = g_YP[e*3+2];
            a0 += w * (Y0*b0 + Y1*b1 + Y2*b2);
        }
        g_aggs[n*64 + 32 + u] = a0 * ISQRT3F * INV_NB;
    } else if (k == 2) {
        for (int e = t0; e < t1; e++) {
            float w = g_w[e*128 + tid];
            int src = g_srcP[e];
            float m = w * g_xs[src*32 + u];
            a0 += m * g_YP[e*3+0];
            a1 += m * g_YP[e*3+1];
            a2 += m * g_YP[e*3+2];
        }
        g_aggv[n*192 +       u] = a0 * INV_NB;
        g_aggv[n*192 +  64 + u] = a1 * INV_NB;
        g_aggv[n*192 + 128 + u] = a2 * INV_NB;
    } else {
        for (int e = t0; e < t1; e++) {
            float w = g_w[e*128 + tid];
            int src = g_srcP[e];
            a0 += w * g_xv[src*96 + u];
            a1 += w * g_xv[src*96 + 32 + u];
            a2 += w * g_xv[src*96 + 64 + u];
        }
        g_aggv[n*192 +  32 + u] = a0 * INV_NB;
        g_aggv[n*192 +  96 + u] = a1 * INV_NB;
        g_aggv[n*192 + 160 + u] = a2 * INV_NB;
    }
}

// ---------------- fctp #2 + gated state update ----------------
__global__ void k_fctp2(const float* __restrict__ attr,
                        const float* __restrict__ W20, const float* __restrict__ W21,
                        int N) {
    extern __shared__ float sm[];
    float* s0 = sm; float* s1 = sm + 8192;
    for (int i = threadIdx.x; i < 8192; i += blockDim.x) { s0[i] = W20[i]; s1[i] = W21[i]; }
    __syncthreads();
    int lane = threadIdx.x & 31;
    int wid  = blockIdx.x * (blockDim.x >> 5) + (threadIdx.x >> 5);
    int wstr = gridDim.x * (blockDim.x >> 5);
    for (int n = wid; n < N; n += wstr) {
        float sa = g_aggs[n*64 + lane],       sb = g_aggs[n*64 + 32 + lane];
        float va0 = g_aggv[n*192 + lane],       vb0 = g_aggv[n*192 + 32 + lane];
        float va1 = g_aggv[n*192 + 64 + lane],  vb1 = g_aggv[n*192 + 96 + lane];
        float va2 = g_aggv[n*192 + 128 + lane], vb2 = g_aggv[n*192 + 160 + lane];
        float at[4] = {attr[n*4+0], attr[n*4+1], attr[n*4+2], attr[n*4+3]};
        float os=0.f, ov0=0.f, ov1=0.f, ov2=0.f;
        for (int u = 0; u < 32; u++) {
            float su  = __shfl_sync(0xffffffffu, sa, u);
            float w0  = __shfl_sync(0xffffffffu, va0, u);
            float w1  = __shfl_sync(0xffffffffu, va1, u);
            float w2  = __shfl_sync(0xffffffffu, va2, u);
            int base = u*128 + lane;
#pragma unroll
            for (int a = 0; a < 4; a++) {
                float ca = at[a];
                int wi = base + a*32;
                os  += su*ca * s0[wi];
                float W = s1[wi];
                ov0 += w0*ca*W; ov1 += w1*ca*W; ov2 += w2*ca*W;
            }
        }
        for (int u = 0; u < 32; u++) {
            float su  = __shfl_sync(0xffffffffu, sb, u);
            float w0  = __shfl_sync(0xffffffffu, vb0, u);
            float w1  = __shfl_sync(0xffffffffu, vb1, u);
            float w2  = __shfl_sync(0xffffffffu, vb2, u);
            int base = (u+32)*128 + lane;
#pragma unroll
            for (int a = 0; a < 4; a++) {
                float ca = at[a];
                int wi = base + a*32;
                os  += su*ca * s0[wi];
                float W = s1[wi];
                ov0 += w0*ca*W; ov1 += w1*ca*W; ov2 += w2*ca*W;
            }
        }
        os *= NORM256; ov0 *= NORM256; ov1 *= NORM256; ov2 *= NORM256;
        float sn  = C_S * g_scs[n*32+lane] + C_X * os;
        float sig = 1.0f / (1.0f + __expf(-sn));
        g_s[n*32+lane] += sn * sig;
        float vn0 = C_S * g_scv[n*96+lane]      + C_X * ov0;
        float vn1 = C_S * g_scv[n*96+32+lane]   + C_X * ov1;
        float vn2 = C_S * g_scv[n*96+64+lane]   + C_X * ov2;
        g_v[n*96+lane]      += vn0 * sig;
        g_v[n*96+32+lane]   += vn1 * sig;
        g_v[n*96+64+lane]   += vn2 * sig;
    }
}

// ---------------- readout + pooling ----------------
__global__ void k_zero_out(float* out) { out[threadIdx.x] = 0.0f; }

__global__ void k_read(const float* __restrict__ attr, const int* __restrict__ batch,
                       const float* __restrict__ Wread, float* __restrict__ out,
                       int N, float poolscale) {
    __shared__ float shW[2048];
    __shared__ float pool[128];
    for (int i = threadIdx.x; i < 2048; i += blockDim.x) shW[i] = Wread[i];
    if (threadIdx.x < 128) pool[threadIdx.x] = 0.0f;
    __syncthreads();
    int lane = threadIdx.x & 31;
    int wid  = blockIdx.x * (blockDim.x >> 5) + (threadIdx.x >> 5);
    int wstr = gridDim.x * (blockDim.x >> 5);
    int w = lane & 15;
    for (int n = wid; n < N; n += wstr) {
        float sl = g_s[n*32 + lane];
        float at[4] = {attr[n*4+0], attr[n*4+1], attr[n*4+2], attr[n*4+3]};
        float acc = 0.f;
        for (int u = 0; u < 32; u++) {
            float su = __shfl_sync(0xffffffffu, sl, u);
            int base = u*64 + w;
#pragma unroll
            for (int a = 0; a < 4; a++) acc += su*at[a]*shW[base + a*16];
        }
        if (lane < 16) {
            int g = batch[n];
            atomicAdd(&pool[g*16 + w], acc * NORM128 * poolscale);
        }
    }
    __syncthreads();
    if (threadIdx.x < 128) atomicAdd(&out[threadIdx.x], pool[threadIdx.x]);
}

// ---------------- launcher ----------------
extern "C" void kernel_launch(void* const* d_in, const int* in_sizes, int n_in,
                              void* d_out, int out_size) {
    const float* x    = (const float*)d_in[0];
    const float* attr = (const float*)d_in[1];
    const float* evec = (const float*)d_in[2];
    const int*   batch= (const int*)  d_in[3];
    const int*   esrc = (const int*)  d_in[4];
    const int*   edst = (const int*)  d_in[5];
    const float* Wsc0 = (const float*)d_in[6];
    const float* Wsc1 = (const float*)d_in[7];
    const float* Wl10 = (const float*)d_in[8];
    const float* Wl11 = (const float*)d_in[9];
    const float* Wfc1 = (const float*)d_in[10];
    const float* Wfc2 = (const float*)d_in[11];
    const float* Wl20 = (const float*)d_in[12];
    const float* Wl21 = (const float*)d_in[13];
    const float* Wread= (const float*)d_in[14];
    int N = in_sizes[0] / 128;
    int E = in_sizes[4];

    cudaFuncSetAttribute(k_fctp1, cudaFuncAttributeMaxDynamicSharedMemorySize, 65536);
    cudaFuncSetAttribute(k_fctp2, cudaFuncAttributeMaxDynamicSharedMemorySize, 65536);

    // CSR build (by dst) + permuted precompute
    k_zero_deg<<<(N + 255) / 256, 256>>>(N);
    k_hist<<<(E + 255) / 256, 256>>>(edst, E);
    k_scan<<<1, SCAN_T>>>(N);
    k_fill<<<(E + 255) / 256, 256>>>(esrc, edst, E);
    k_pre_edges<<<(E + 255) / 256, 256>>>(evec, E);
    k_pre_nodes<<<(N*32 + 255) / 256, 256>>>(x, N);

    for (int l = 0; l < 2; l++) {
        k_fctp1<<<444, 256, 65536>>>(attr, Wsc0 + l*4096, Wsc1 + l*4096,
                                     Wl10 + l*4096, Wl11 + l*4096, N);
        k_wgemm<<<(E + WG_TE - 1) / WG_TE, 256>>>(Wfc1 + l*640, Wfc2 + l*8192, E);
        k_gather2<<<N, 128>>>(N);
        k_fctp2<<<444, 256, 65536>>>(attr, Wl20 + l*8192, Wl21 + l*8192, N);
    }

    k_zero_out<<<1, 128>>>((float*)d_out);
    float poolscale = 1.0f / sqrtf((float)N / 8.0f);
    k_read<<<592, 128>>>(attr, batch, Wread, (float*)d_out, N, poolscale);
}